// round 2
// baseline (speedup 1.0000x reference)
#include <cuda_runtime.h>
#include <cstdint>
#include <math_constants.h>

#define CDIM 256
#define KCODES 8192
#define NROWS 16384
#define TM 64
#define TN 128

// Scratch (device globals: allocation-free per harness rules)
__device__ float g_embT[(size_t)CDIM * KCODES];   // [c][k]
__device__ float g_C[KCODES];                     // ||e_k||^2, strict sequential fp32
__device__ float g_A[NROWS];                      // ||x_n||^2, strict sequential fp32
__device__ float g_partial[NROWS / TM];           // per-block loss partials

// ---------------------------------------------------------------------------
// Prep 1: transpose emb [K,C] -> embT [C,K] (tiled, conflict-free)
// ---------------------------------------------------------------------------
__global__ void transpose_emb_kernel(const float* __restrict__ emb) {
    __shared__ float tile[32][33];
    int kb = blockIdx.x * 32, cb = blockIdx.y * 32;
    int tx = threadIdx.x & 31, ty = threadIdx.x >> 5;   // 256 threads = 32x8
    #pragma unroll
    for (int r = ty; r < 32; r += 8)
        tile[r][tx] = emb[(size_t)(kb + r) * CDIM + cb + tx];
    __syncthreads();
    #pragma unroll
    for (int r = ty; r < 32; r += 8)
        g_embT[(size_t)(cb + r) * KCODES + kb + tx] = tile[tx][r];
}

// ---------------------------------------------------------------------------
// Prep 2: C_k = sum_c e^2, STRICT sequential fp32 (mul then add, ascending c)
// emulating XLA's IEEE-strict reduce. One thread per code.
// ---------------------------------------------------------------------------
__global__ void c_kernel(const float* __restrict__ emb) {
    int k = blockIdx.x * blockDim.x + threadIdx.x;
    if (k >= KCODES) return;
    const float* e = emb + (size_t)k * CDIM;
    float s = 0.f;
    for (int c = 0; c < CDIM; c++) {
        float v = __ldg(e + c);
        s = __fadd_rn(s, __fmul_rn(v, v));
    }
    g_C[k] = s;
}

// ---------------------------------------------------------------------------
// Prep 3: A_n = sum_c z^2, STRICT sequential fp32 ascending c.
// One thread per row; lanes = consecutive hw -> coalesced per c-step.
// ---------------------------------------------------------------------------
__global__ void a_kernel(const float* __restrict__ z) {
    int n = blockIdx.x * blockDim.x + threadIdx.x;
    if (n >= NROWS) return;
    int b = n >> 10, hw = n & 1023;
    const float* zp = z + (size_t)b * CDIM * 1024 + hw;
    float s = 0.f;
    for (int c = 0; c < CDIM; c++) {
        float v = __ldg(zp + (size_t)c * 1024);
        s = __fadd_rn(s, __fmul_rn(v, v));
    }
    g_A[n] = s;
}

// ---------------------------------------------------------------------------
// Main: fused GEMM (fma-chain ascending c) + fp32-emulated distance + argmin
// (first-index tie-break) + gather + quantized_st write + loss partial.
// One block owns TM=64 rows.
// ---------------------------------------------------------------------------
__global__ __launch_bounds__(256, 1)
void vq_main_kernel(const float* __restrict__ z, const float* __restrict__ emb,
                    float* __restrict__ out) {
    extern __shared__ float smem[];
    float* Xs    = smem;                 // [C][TM]  = 16384 f
    float* Es    = Xs + CDIM * TM;       // [C][TN]  = 32768 f
    float* C_s   = Es + CDIM * TN;       // [TN]
    int*   bidx_s = (int*)(C_s + TN);    // [TM]

    const int tid = threadIdx.x;
    const int tm  = tid >> 4;            // 0..15  -> rows tm*4..tm*4+3
    const int tn  = tid & 15;            // 0..15  -> codes tn*8..tn*8+7
    const int n0  = blockIdx.x * TM;
    const int bimg = n0 >> 10;           // batch index
    const int hw0  = n0 & 1023;
    const float* zb = z + (size_t)bimg * CDIM * 1024 + hw0;

    // Load X tile: Xs[c][m], coalesced float4 over m
    float4* Xs4 = (float4*)Xs;
    for (int t4 = tid; t4 < CDIM * TM / 4; t4 += 256) {
        int c = t4 >> 4, m4 = t4 & 15;
        Xs4[t4] = *(const float4*)(zb + (size_t)c * 1024 + m4 * 4);
    }

    // Per-thread row norms A (rows tm*4..tm*4+3)
    float A_r[4];
    #pragma unroll
    for (int i = 0; i < 4; i++) A_r[i] = g_A[n0 + tm * 4 + i];

    float rbv[4] = {CUDART_INF_F, CUDART_INF_F, CUDART_INF_F, CUDART_INF_F};
    int   rbi[4] = {0x7fffffff, 0x7fffffff, 0x7fffffff, 0x7fffffff};
    float4* Es4 = (float4*)Es;

    for (int k0 = 0; k0 < KCODES; k0 += TN) {
        __syncthreads();   // protect Es/C_s from previous chunk's readers
        for (int t4 = tid; t4 < CDIM * TN / 4; t4 += 256) {
            int c = t4 >> 5, kq = t4 & 31;
            Es4[t4] = *(const float4*)(g_embT + (size_t)c * KCODES + k0 + kq * 4);
        }
        if (tid < TN) C_s[tid] = g_C[k0 + tid];
        __syncthreads();

        float acc[4][8];
        #pragma unroll
        for (int i = 0; i < 4; i++)
            #pragma unroll
            for (int j = 0; j < 8; j++) acc[i][j] = 0.f;

        // Sequential FMA chain over c ascending: matches Eigen/SGEMM accumulation
        #pragma unroll 8
        for (int cc = 0; cc < CDIM; cc++) {
            float4 a  = Xs4[cc * 16 + tm];
            float4 b0 = Es4[cc * 32 + tn * 2];
            float4 b1 = Es4[cc * 32 + tn * 2 + 1];
            float av[4]  = {a.x, a.y, a.z, a.w};
            float bw[8]  = {b0.x, b0.y, b0.z, b0.w, b1.x, b1.y, b1.z, b1.w};
            #pragma unroll
            for (int i = 0; i < 4; i++)
                #pragma unroll
                for (int j = 0; j < 8; j++)
                    acc[i][j] = __fmaf_rn(av[i], bw[j], acc[i][j]);
        }

        // Emulated reference distance: d = fl(fl(A - fl(2P)) + C), argmin
        int kbase = k0 + tn * 8;
        #pragma unroll
        for (int i = 0; i < 4; i++) {
            float bv = CUDART_INF_F; int bi = 0x7fffffff;
            #pragma unroll
            for (int j = 0; j < 8; j++) {
                float t = __fsub_rn(A_r[i], __fmul_rn(2.0f, acc[i][j]));
                float d = __fadd_rn(t, C_s[tn * 8 + j]);
                if (d < bv) { bv = d; bi = kbase + j; }   // ascending j: first-min kept
            }
            // reduce over tn (16 lanes per half-warp), lowest index wins ties
            #pragma unroll
            for (int off = 8; off; off >>= 1) {
                float ov = __shfl_down_sync(0xffffffffu, bv, off);
                int   oi = __shfl_down_sync(0xffffffffu, bi, off);
                if (ov < bv || (ov == bv && oi < bi)) { bv = ov; bi = oi; }
            }
            if (tn == 0 && (bv < rbv[i] || (bv == rbv[i] && bi < rbi[i]))) {
                rbv[i] = bv; rbi[i] = bi;
            }
        }
    }
    __syncthreads();
    if (tn == 0) {
        #pragma unroll
        for (int i = 0; i < 4; i++) bidx_s[tm * 4 + i] = rbi[i];
    }
    __syncthreads();

    // indices output (float32; layout: q | cb_loss | commit_loss | idx)
    const size_t QELEMS = (size_t)NROWS * CDIM;
    if (tid < TM) out[QELEMS + 2 + n0 + tid] = (float)bidx_s[tid];

    // quantized_st = fl(z + fl(q - z)); accumulate fl(q-z)^2 for losses
    float lsum = 0.f;
    for (int e = tid; e < TM * CDIM; e += 256) {
        int c = e >> 6, m = e & 63;
        float q  = emb[(size_t)bidx_s[m] * CDIM + c];
        float zv = zb[(size_t)c * 1024 + m];
        float d  = __fsub_rn(q, zv);
        out[(size_t)bimg * CDIM * 1024 + (size_t)c * 1024 + hw0 + m] = __fadd_rn(zv, d);
        lsum = __fmaf_rn(d, d, lsum);
    }

    // deterministic block reduction (Xs region is free now)
    __syncthreads();
    Xs[tid] = lsum;
    __syncthreads();
    #pragma unroll
    for (int st = 128; st; st >>= 1) {
        if (tid < st) Xs[tid] += Xs[tid + st];
        __syncthreads();
    }
    if (tid == 0) g_partial[blockIdx.x] = Xs[0];
}

// ---------------------------------------------------------------------------
// Finalize losses
// ---------------------------------------------------------------------------
__global__ void finalize_kernel(float* __restrict__ out) {
    __shared__ float red[256];
    red[threadIdx.x] = g_partial[threadIdx.x];   // exactly NROWS/TM = 256 partials
    __syncthreads();
    #pragma unroll
    for (int st = 128; st; st >>= 1) {
        if (threadIdx.x < st) red[threadIdx.x] += red[threadIdx.x + st];
        __syncthreads();
    }
    if (threadIdx.x == 0) {
        const size_t QELEMS = (size_t)NROWS * CDIM;
        float loss = red[0] / (float)QELEMS;
        out[QELEMS]     = loss;          // codebook loss
        out[QELEMS + 1] = 0.25f * loss;  // commitment loss (BETA=0.25)
    }
}

// ---------------------------------------------------------------------------
extern "C" void kernel_launch(void* const* d_in, const int* in_sizes, int n_in,
                              void* d_out, int out_size) {
    const float* z   = (const float*)d_in[0];
    const float* emb = (const float*)d_in[1];
    float* out = (float*)d_out;

    constexpr size_t SMEM =
        (size_t)(CDIM * TM + CDIM * TN + TN) * sizeof(float) + TM * sizeof(int);
    cudaFuncSetAttribute(vq_main_kernel,
                         cudaFuncAttributeMaxDynamicSharedMemorySize, (int)SMEM);

    transpose_emb_kernel<<<dim3(KCODES / 32, CDIM / 32), 256>>>(emb);
    c_kernel<<<KCODES / 256, 256>>>(emb);
    a_kernel<<<NROWS / 256, 256>>>(z);
    vq_main_kernel<<<NROWS / TM, 256, SMEM>>>(z, emb, out);
    finalize_kernel<<<1, 256>>>(out);
}